// round 16
// baseline (speedup 1.0000x reference)
#include <cuda_runtime.h>
#include <cuda_fp16.h>
#include <cstdint>
#include <cstddef>

#define DIMV 1024
#define NB 4
#define NSEQ 1024
#define NH 16
#define DH 64
#define MROWS (NB * NSEQ)

// ---------------- scratch (static device globals; no allocs) ----------------
__device__ __half g_act[MROWS * DIMV];       // Q activations / ln0 fp16
__device__ __half g_act2[MROWS * DIMV];      // K activations fp16
__device__ __half g_w[4][DIMV * DIMV];       // Wq, Wk, Wv, Wo fp16
__device__ __half g_qh[MROWS * DIMV];
__device__ __half g_kh[MROWS * DIMV];
__device__ __half g_vh[MROWS * DIMV];
__device__ __half g_atth[MROWS * DIMV];      // attn out fp16, then reused for u fp16

// ======================================================================
// PTX helpers (compute_103-safe)
// ======================================================================
__device__ __forceinline__ uint32_t smem_u32(const void* p) {
    uint32_t a;
    asm("{ .reg .u64 t; cvta.to.shared.u64 t, %1; cvt.u32.u64 %0, t; }" : "=r"(a) : "l"(p));
    return a;
}
__device__ __forceinline__ void cp_async16(uint32_t dst, const void* src) {
    asm volatile("cp.async.cg.shared.global [%0], [%1], 16;" :: "r"(dst), "l"(src));
}
__device__ __forceinline__ void cp_commit() {
    asm volatile("cp.async.commit_group;" ::: "memory");
}
template <int N>
__device__ __forceinline__ void cp_wait() {
    asm volatile("cp.async.wait_group %0;" :: "n"(N) : "memory");
}
__device__ __forceinline__ void ldsm4(uint32_t& r0, uint32_t& r1, uint32_t& r2,
                                      uint32_t& r3, uint32_t addr) {
    asm volatile("ldmatrix.sync.aligned.m8n8.x4.shared.b16 {%0,%1,%2,%3}, [%4];"
                 : "=r"(r0), "=r"(r1), "=r"(r2), "=r"(r3) : "r"(addr));
}
__device__ __forceinline__ void ldsm4t(uint32_t& r0, uint32_t& r1, uint32_t& r2,
                                       uint32_t& r3, uint32_t addr) {
    asm volatile("ldmatrix.sync.aligned.m8n8.x4.trans.shared.b16 {%0,%1,%2,%3}, [%4];"
                 : "=r"(r0), "=r"(r1), "=r"(r2), "=r"(r3) : "r"(addr));
}
__device__ __forceinline__ void mma_f16(float& c0, float& c1, float& c2, float& c3,
                                        uint32_t a0, uint32_t a1, uint32_t a2, uint32_t a3,
                                        uint32_t b0, uint32_t b1) {
    asm volatile(
        "mma.sync.aligned.m16n8k16.row.col.f32.f16.f16.f32 "
        "{%0,%1,%2,%3}, {%4,%5,%6,%7}, {%8,%9}, {%0,%1,%2,%3};"
        : "+f"(c0), "+f"(c1), "+f"(c2), "+f"(c3)
        : "r"(a0), "r"(a1), "r"(a2), "r"(a3), "r"(b0), "r"(b1));
}
__device__ __forceinline__ uint32_t packh(float a, float b) {
    __half2 t = __floats2half2_rn(a, b);
    return *(uint32_t*)&t;
}
__device__ __forceinline__ float2 unpackh(uint32_t u) {
    __half2 h = *(__half2*)&u;
    return __half22float2(h);
}

// ======================================================================
// GEMM core via fp16 HMMA: V[m,n] = sum_k A[m,k]*W[n,k] + bias[n]
// 128x128 tile, BK=64, 8 warps (2x4), 3-stage, ONE __syncthreads per
// 64-wide K iteration (16 barriers total vs 32 at BK=32).
// Row layout 144B (128B data + 16B pad), conflict-free ldmatrix.
// ======================================================================
#define GROWB 144
#define GBUF (128 * GROWB)      // 18432 per operand
#define STAGEB (2 * GBUF)       // 36864
#define G_SMEM (3 * STAGEB)     // 110592

__device__ __forceinline__ void gemm_core(
    uint32_t sb, const __half* __restrict__ ah, const __half* __restrict__ bh,
    int m0, int n0, const float* __restrict__ bias,
    __half* __restrict__ Ch, const __half* __restrict__ lnref) {
    const int tid = threadIdx.x;
    const int lane = tid & 31;
    const int wid = tid >> 5;
    const int wm = wid >> 2;
    const int wn = wid & 3;

    // per stage: 2 bufs x 128 rows x 8 x 16B = 2048 chunks, 8 per thread
    auto issue = [&](int kt, int st) {
        const int k0 = kt * 64;
        const uint32_t base = sb + st * STAGEB;
#pragma unroll
        for (int i = 0; i < 8; i++) {
            const int c = tid + i * 256;      // 0..2047
            const int buf = c >> 10;          // 0:A 1:B
            const int row = (c >> 3) & 127;
            const int seg = c & 7;
            const __half* src = (buf ? bh + (size_t)(n0 + row) * DIMV
                                     : ah + (size_t)(m0 + row) * DIMV) + k0 + seg * 8;
            cp_async16(base + buf * GBUF + row * GROWB + seg * 16, src);
        }
        cp_commit();
    };

    float acc[4][4][4];
#pragma unroll
    for (int mt = 0; mt < 4; mt++)
#pragma unroll
        for (int nt = 0; nt < 4; nt++)
#pragma unroll
            for (int r = 0; r < 4; r++) acc[mt][nt][r] = 0.0f;

    issue(0, 0);
    issue(1, 1);

    const int NKT = DIMV / 64;   // 16
    for (int kt = 0; kt < NKT; ++kt) {
        if (kt + 1 < NKT) cp_wait<1>();
        else              cp_wait<0>();
        __syncthreads();

        const uint32_t stg = sb + (kt % 3) * STAGEB;
        const int arow = lane & 15;
        const int akh = lane >> 4;
        const int bprow = ((lane >> 4) << 3) + (lane & 7);
        const int bpkh = (lane >> 3) & 1;

#pragma unroll
        for (int ks = 0; ks < 4; ks++) {      // four k16 steps per 64-chunk
            const uint32_t koff = ks * 32;
            uint32_t fa[4][4];
#pragma unroll
            for (int mt = 0; mt < 4; mt++) {
                const uint32_t ra = stg +
                    (uint32_t)(wm * 64 + mt * 16 + arow) * GROWB + koff + akh * 16;
                ldsm4(fa[mt][0], fa[mt][1], fa[mt][2], fa[mt][3], ra);
            }
#pragma unroll
            for (int ntp = 0; ntp < 2; ntp++) {
                const uint32_t rb = stg + GBUF +
                    (uint32_t)(wn * 32 + ntp * 16 + bprow) * GROWB + koff + bpkh * 16;
                uint32_t b0, b1, b2, b3;
                ldsm4(b0, b1, b2, b3, rb);
                const int nt = ntp * 2;
#pragma unroll
                for (int mt = 0; mt < 4; mt++) {
                    mma_f16(acc[mt][nt][0], acc[mt][nt][1], acc[mt][nt][2], acc[mt][nt][3],
                            fa[mt][0], fa[mt][1], fa[mt][2], fa[mt][3], b0, b1);
                    mma_f16(acc[mt][nt + 1][0], acc[mt][nt + 1][1],
                            acc[mt][nt + 1][2], acc[mt][nt + 1][3],
                            fa[mt][0], fa[mt][1], fa[mt][2], fa[mt][3], b2, b3);
                }
            }
        }
        // write stage (kt+2)%3 = (kt-1)%3: last read in iteration kt-1,
        // separated from this write by the barrier at the top of kt.
        if (kt + 2 < NKT) issue(kt + 2, (kt + 2) % 3);
    }

    const int cr = lane >> 2;
    const int cc = (lane & 3) * 2;
#pragma unroll
    for (int nt = 0; nt < 4; nt++) {
        const int col = n0 + wn * 32 + nt * 8 + cc;
        const float2 bf = *(const float2*)(bias + col);
#pragma unroll
        for (int mt = 0; mt < 4; mt++) {
            const int r0 = m0 + wm * 64 + mt * 16 + cr;
            float v00 = acc[mt][nt][0] + bf.x, v01 = acc[mt][nt][1] + bf.y;
            float v10 = acc[mt][nt][2] + bf.x, v11 = acc[mt][nt][3] + bf.y;
            if (lnref) {
                float2 l0 = unpackh(*(const uint32_t*)(lnref + (size_t)r0 * DIMV + col));
                float2 l1 = unpackh(*(const uint32_t*)(lnref + (size_t)(r0 + 8) * DIMV + col));
                v00 = l0.x + fmaxf(v00, 0.0f);
                v01 = l0.y + fmaxf(v01, 0.0f);
                v10 = l1.x + fmaxf(v10, 0.0f);
                v11 = l1.y + fmaxf(v11, 0.0f);
            }
            *(uint32_t*)(Ch + (size_t)r0 * DIMV + col) = packh(v00, v01);
            *(uint32_t*)(Ch + (size_t)(r0 + 8) * DIMV + col) = packh(v10, v11);
        }
    }
}

__global__ __launch_bounds__(256, 2)
void gemm_qkv(const __half* __restrict__ act, const __half* __restrict__ act2,
              const __half* __restrict__ w,
              const float* __restrict__ bq, const float* __restrict__ bk,
              const float* __restrict__ bv,
              __half* __restrict__ pqh, __half* __restrict__ pkh,
              __half* __restrict__ pvh) {
    extern __shared__ char smc[];
    const uint32_t sb = smem_u32(smc);
    const int x = blockIdx.x;
    const int m0 = blockIdx.y * 128;
    const __half *A, *B;
    const float* bias;
    __half* Ch;
    int n0;
    if (x < 8) {
        A = act;  B = w;                           bias = bq; Ch = pqh; n0 = x * 128;
    } else if (x < 16) {
        A = act2; B = w + (size_t)DIMV * DIMV;     bias = bk; Ch = pkh; n0 = (x - 8) * 128;
    } else {
        A = act2; B = w + (size_t)2 * DIMV * DIMV; bias = bv; Ch = pvh; n0 = (x - 16) * 128;
    }
    gemm_core(sb, A, B, m0, n0, bias, Ch, nullptr);
}

__global__ __launch_bounds__(256, 2)
void gemm_wo(const __half* __restrict__ act, const __half* __restrict__ w3,
             const float* __restrict__ bo, __half* __restrict__ u) {
    extern __shared__ char smc[];
    const uint32_t sb = smem_u32(smc);
    gemm_core(sb, act, w3, blockIdx.y * 128, blockIdx.x * 128, bo, u, act);
}

// ======================================================================
// One-shot convert: 4 weights + Q act + K act -> fp16 (4 float4/thread ILP)
// ======================================================================
#define W4TOT (DIMV * DIMV)
#define ACTTOT (MROWS * DIMV)
#define CONV_TOT (4 * W4TOT / 4 + 2 * ACTTOT / 4)
__global__ __launch_bounds__(256) void conv_all(const float* __restrict__ Wq,
                                                const float* __restrict__ Wk,
                                                const float* __restrict__ Wv,
                                                const float* __restrict__ Wo,
                                                const float* __restrict__ Qa,
                                                const float* __restrict__ Ka,
                                                __half* __restrict__ wout,
                                                __half* __restrict__ qout,
                                                __half* __restrict__ kout) {
    const int W4Q = W4TOT / 4;
    const int A4 = ACTTOT / 4;
    auto locate = [&](int i, const float*& src, __half*& dst, int& off) {
        if (i < 4 * W4Q) {
            const int wsel = i >> 18;
            off = i & (W4Q - 1);
            src = (wsel == 0) ? Wq : (wsel == 1) ? Wk : (wsel == 2) ? Wv : Wo;
            dst = wout + (size_t)wsel * W4TOT;
        } else if (i < 4 * W4Q + A4) {
            off = i - 4 * W4Q;
            src = Qa;
            dst = qout;
        } else {
            off = i - 4 * W4Q - A4;
            src = Ka;
            dst = kout;
        }
    };
    const int base = blockIdx.x * 1024 + threadIdx.x;
    const float* s[4];
    __half* d[4];
    int o[4];
#pragma unroll
    for (int j = 0; j < 4; j++) locate(base + j * 256, s[j], d[j], o[j]);
    float4 v[4];
#pragma unroll
    for (int j = 0; j < 4; j++) v[j] = ((const float4*)s[j])[o[j]];
#pragma unroll
    for (int j = 0; j < 4; j++) {
        uint2 r = {packh(v[j].x, v[j].y), packh(v[j].z, v[j].w)};
        ((uint2*)d[j])[o[j]] = r;
    }
}

// ======================================================================
// Flash attention via fp16 HMMA (proven R9/R13/R15 structure, unchanged)
// ======================================================================
#define AROWB 144
#define ABUF (128 * AROWB)          // 18432
#define ASTAGE (2 * ABUF)           // 36864
#define AQOFF (2 * ASTAGE)          // 73728
#define A_SMEM (AQOFF + ABUF)       // 92160

__global__ __launch_bounds__(256, 2)
void attn_flash(const __half* __restrict__ qh, const __half* __restrict__ kh,
                const __half* __restrict__ vh, const float* __restrict__ bias,
                __half* __restrict__ out) {
    extern __shared__ char smc[];
    const uint32_t sb = smem_u32(smc);
    const int tid = threadIdx.x;
    const int lane = tid & 31;
    const int w = tid >> 5;
    const int q0 = blockIdx.x * 128;
    const int hb = blockIdx.y;
    const int h = hb >> 2;
    const int b = hb & 3;
    const size_t rowbase = (size_t)b * NSEQ;
    const int hcol = h * DH;

    {
#pragma unroll
        for (int i = 0; i < 4; i++) {
            const int c = tid + i * 256;
            const int row = c >> 3;
            const int seg = c & 7;
            cp_async16(sb + AQOFF + row * AROWB + seg * 16,
                       qh + (rowbase + q0 + row) * DIMV + hcol + seg * 8);
        }
        cp_commit();
    }
    auto issueKV = [&](int k0, int st) {
#pragma unroll
        for (int i = 0; i < 8; i++) {
            const int c = tid + i * 256;
            const int buf = c >> 10;
            const int row = (c >> 3) & 127;
            const int seg = c & 7;
            const __half* src = (buf ? vh : kh) + (rowbase + k0 + row) * DIMV + hcol + seg * 8;
            cp_async16(sb + st * ASTAGE + buf * ABUF + row * AROWB + seg * 16, src);
        }
        cp_commit();
    };
    issueKV(0, 0);

    float oacc[8][4];
#pragma unroll
    for (int d = 0; d < 8; d++)
#pragma unroll
        for (int r = 0; r < 4; r++) oacc[d][r] = 0.0f;
    float lsum0 = 0.0f, lsum1 = 0.0f;
    const float scale = 0.03125f;
    const float* bb = bias + ((size_t)hb * NSEQ + q0) * NSEQ;
    const int r_lo = lane >> 2;
    const int c_lo = (lane & 3) * 2;
    const size_t brow0 = (size_t)(w * 16 + r_lo) * NSEQ;

    float2 bA[8], bB[8];
    auto load_bias_q = [&](float2* slot, int ckx, int gq) {
        const float* bcol = bb + ckx * 128 + gq * 32;
#pragma unroll
        for (int nl = 0; nl < 4; nl++) {
            slot[nl * 2] = __ldcs((const float2*)(bcol + brow0 + nl * 8 + c_lo));
            slot[nl * 2 + 1] =
                __ldcs((const float2*)(bcol + brow0 + 8 * NSEQ + nl * 8 + c_lo));
        }
    };
    load_bias_q(bA, 0, 0);
    load_bias_q(bB, 0, 1);

    uint32_t qf[2][2][4];
    bool qloaded = false;

    for (int ck = 0; ck < 8; ck++) {
        const int st = ck & 1;
        if (ck + 1 < 8) {
            issueKV((ck + 1) * 128, (ck + 1) & 1);
            cp_wait<1>();
        } else {
            cp_wait<0>();
        }
        __syncthreads();
        const uint32_t kbase = sb + st * ASTAGE;

        if (!qloaded) {
            qloaded = true;
            const int arow = lane & 15;
            const int akh = lane >> 4;
#pragma unroll
            for (int ksp = 0; ksp < 2; ksp++) {
                const uint32_t ra = sb + AQOFF +
                    (uint32_t)(w * 16 + arow) * AROWB + ksp * 64 + akh * 16;
                ldsm4(qf[ksp][0][0], qf[ksp][0][1], qf[ksp][0][2], qf[ksp][0][3], ra);
                ldsm4(qf[ksp][1][0], qf[ksp][1][1], qf[ksp][1][2], qf[ksp][1][3], ra + 32);
            }
        }

#pragma unroll
        for (int h2 = 0; h2 < 2; h2++) {
#pragma unroll
            for (int qq = 0; qq < 2; qq++) {
                float sacc[4][4];
#pragma unroll
                for (int nl = 0; nl < 4; nl++) {
                    sacc[nl][0] = 0.0f; sacc[nl][1] = 0.0f;
                    sacc[nl][2] = 0.0f; sacc[nl][3] = 0.0f;
                }
#pragma unroll
                for (int ksp = 0; ksp < 2; ksp++) {
#pragma unroll
                    for (int nl = 0; nl < 4; nl++) {
                        const uint32_t rb = kbase +
                            (uint32_t)(h2 * 64 + qq * 32 + nl * 8 + (lane & 7)) * AROWB +
                            ksp * 64 + ((lane >> 3) & 3) * 16;
                        uint32_t b0, b1, b2, b3;
                        ldsm4(b0, b1, b2, b3, rb);
                        mma_f16(sacc[nl][0], sacc[nl][1], sacc[nl][2], sacc[nl][3],
                                qf[ksp][0][0], qf[ksp][0][1], qf[ksp][0][2], qf[ksp][0][3],
                                b0, b1);
                        mma_f16(sacc[nl][0], sacc[nl][1], sacc[nl][2], sacc[nl][3],
                                qf[ksp][1][0], qf[ksp][1][1], qf[ksp][1][2], qf[ksp][1][3],
                                b2, b3);
                    }
                }

                float2* slot = qq ? bB : bA;
                uint32_t pa[2][4];
#pragma unroll
                for (int nl = 0; nl < 4; nl++) {
                    float2 b01 = slot[nl * 2];
                    float2 b23 = slot[nl * 2 + 1];
                    float p0 = __expf(fmaf(sacc[nl][0], scale, b01.x));
                    float p1 = __expf(fmaf(sacc[nl][1], scale, b01.y));
                    float p2 = __expf(fmaf(sacc[nl][2], scale, b23.x));
                    float p3 = __expf(fmaf(sacc[nl][3], scale, b23.y));
                    lsum0 += p0 + p1;
                    lsum1 += p2 + p3;
                    pa[nl >> 1][(nl & 1) * 2] = packh(p0, p1);
                    pa[nl >> 1][(nl & 1) * 2 + 1] = packh(p2, p3);
                }

                {
                    const int gq = h2 * 2 + qq;
                    int nq = gq + 2;
                    int nck = ck;
                    if (nq >= 4) { nq -= 4; nck++; }
                    if (nck < 8) load_bias_q(slot, nck, nq);
                }

#pragma unroll
                for (int kt = 0; kt < 2; kt++) {
#pragma unroll
                    for (int dtp = 0; dtp < 4; dtp++) {
                        const int dt = dtp * 2;
                        const uint32_t rv = kbase + ABUF +
                            (uint32_t)(h2 * 64 + qq * 32 + kt * 16 + (lane & 15)) * AROWB +
                            (dt + (lane >> 4)) * 16;
                        uint32_t v0, v1, v2, v3;
                        ldsm4t(v0, v1, v2, v3, rv);
                        mma_f16(oacc[dt][0], oacc[dt][1], oacc[dt][2], oacc[dt][3],
                                pa[kt][0], pa[kt][1], pa[kt][2], pa[kt][3], v0, v1);
                        mma_f16(oacc[dt + 1][0], oacc[dt + 1][1],
                                oacc[dt + 1][2], oacc[dt + 1][3],
                                pa[kt][0], pa[kt][1], pa[kt][2], pa[kt][3], v2, v3);
                    }
                }
            }
        }
        __syncthreads();
    }

    lsum0 += __shfl_xor_sync(0xffffffffu, lsum0, 1);
    lsum0 += __shfl_xor_sync(0xffffffffu, lsum0, 2);
    lsum1 += __shfl_xor_sync(0xffffffffu, lsum1, 1);
    lsum1 += __shfl_xor_sync(0xffffffffu, lsum1, 2);
    const float inv0 = 1.0f / lsum0;
    const float inv1 = 1.0f / lsum1;
    const size_t r0g = rowbase + q0 + w * 16 + r_lo;
#pragma unroll
    for (int dt = 0; dt < 8; dt++) {
        const int col = hcol + dt * 8 + c_lo;
        float2 q01 = unpackh(*(const uint32_t*)(qh + r0g * DIMV + col));
        float2 q23 = unpackh(*(const uint32_t*)(qh + (r0g + 8) * DIMV + col));
        *(uint32_t*)(out + r0g * DIMV + col) =
            packh(q01.x + oacc[dt][0] * inv0, q01.y + oacc[dt][1] * inv0);
        *(uint32_t*)(out + (r0g + 8) * DIMV + col) =
            packh(q23.x + oacc[dt][2] * inv1, q23.y + oacc[dt][3] * inv1);
    }
}

// ======================================================================
// LayerNorm (fp16 in) -> fp16 out (block version, known-good)
// ======================================================================
__global__ __launch_bounds__(256) void ln_fused(const __half* __restrict__ x,
                                                const float* __restrict__ gamma,
                                                const float* __restrict__ beta,
                                                __half* __restrict__ hi) {
    const int row = blockIdx.x;
    const int tid = threadIdx.x;
    uint2 raw = *(const uint2*)(x + (size_t)row * DIMV + tid * 4);
    float2 v01 = unpackh(raw.x);
    float2 v23 = unpackh(raw.y);
    float4 v = {v01.x, v01.y, v23.x, v23.y};
    float s = v.x + v.y + v.z + v.w;
    float sq = v.x * v.x + v.y * v.y + v.z * v.z + v.w * v.w;
#pragma unroll
    for (int o = 16; o; o >>= 1) {
        s += __shfl_xor_sync(0xffffffffu, s, o);
        sq += __shfl_xor_sync(0xffffffffu, sq, o);
    }
    __shared__ float sh[18];
    int wid = tid >> 5, lane = tid & 31;
    if (lane == 0) { sh[wid] = s; sh[8 + wid] = sq; }
    __syncthreads();
    if (tid == 0) {
        float S = 0.0f, SQ = 0.0f;
        for (int i = 0; i < 8; i++) { S += sh[i]; SQ += sh[8 + i]; }
        float m = S * (1.0f / DIMV);
        float var = SQ * (1.0f / DIMV) - m * m;
        sh[16] = m;
        sh[17] = rsqrtf(var + 1e-5f);
    }
    __syncthreads();
    float m = sh[16], rs = sh[17];
    float4 gv = *(const float4*)(gamma + tid * 4);
    float4 bv = *(const float4*)(beta + tid * 4);
    float o0 = (v.x - m) * rs * gv.x + bv.x;
    float o1 = (v.y - m) * rs * gv.y + bv.y;
    float o2 = (v.z - m) * rs * gv.z + bv.z;
    float o3 = (v.w - m) * rs * gv.w + bv.w;
    uint2 r = {packh(o0, o1), packh(o2, o3)};
    *(uint2*)(hi + (size_t)row * DIMV + tid * 4) = r;
}

// Final: pure LayerNorm of u (fp16 in, fp32 out)
__global__ __launch_bounds__(256) void final_kernel(const __half* __restrict__ x,
                                                    const float* __restrict__ gamma,
                                                    const float* __restrict__ beta,
                                                    float* __restrict__ y) {
    const int row = blockIdx.x;
    const int tid = threadIdx.x;
    uint2 raw = *(const uint2*)(x + (size_t)row * DIMV + tid * 4);
    float2 v01 = unpackh(raw.x);
    float2 v23 = unpackh(raw.y);
    float4 v = {v01.x, v01.y, v23.x, v23.y};
    float s = v.x + v.y + v.z + v.w;
    float sq = v.x * v.x + v.y * v.y + v.z * v.z + v.w * v.w;
#pragma unroll
    for (int o = 16; o; o >>= 1) {
        s += __shfl_xor_sync(0xffffffffu, s, o);
        sq += __shfl_xor_sync(0xffffffffu, sq, o);
    }
    __shared__ float sh[18];
    int wid = tid >> 5, lane = tid & 31;
    if (lane == 0) { sh[wid] = s; sh[8 + wid] = sq; }
    __syncthreads();
    if (tid == 0) {
        float S = 0.0f, SQ = 0.0f;
        for (int i = 0; i < 8; i++) { S += sh[i]; SQ += sh[8 + i]; }
        float m = S * (1.0f / DIMV);
        float var = SQ * (1.0f / DIMV) - m * m;
        sh[16] = m;
        sh[17] = rsqrtf(var + 1e-5f);
    }
    __syncthreads();
    float m = sh[16], rs = sh[17];
    float4 gv = *(const float4*)(gamma + tid * 4);
    float4 bv = *(const float4*)(beta + tid * 4);
    float4 o;
    o.x = (v.x - m) * rs * gv.x + bv.x;
    o.y = (v.y - m) * rs * gv.y + bv.y;
    o.z = (v.z - m) * rs * gv.z + bv.z;
    o.w = (v.w - m) * rs * gv.w + bv.w;
    *(float4*)(y + (size_t)row * DIMV + tid * 4) = o;
}

// ======================================================================
extern "C" void kernel_launch(void* const* d_in, const int* in_sizes, int n_in,
                              void* d_out, int out_size) {
    (void)in_sizes; (void)n_in; (void)out_size;
    const float* Q   = (const float*)d_in[0];
    const float* Kin = (const float*)d_in[1];
    const float* sbias = (const float*)d_in[2];
    const float* Wq  = (const float*)d_in[3];
    const float* bq  = (const float*)d_in[4];
    const float* Wk  = (const float*)d_in[5];
    const float* bk  = (const float*)d_in[6];
    const float* Wv  = (const float*)d_in[7];
    const float* bv  = (const float*)d_in[8];
    const float* Wo  = (const float*)d_in[9];
    const float* bo  = (const float*)d_in[10];
    const float* g0  = (const float*)d_in[11];
    const float* be0 = (const float*)d_in[12];
    const float* g1  = (const float*)d_in[13];
    const float* be1 = (const float*)d_in[14];
    float* out = (float*)d_out;

    __half *act, *act2, *pw, *pqh, *pkh, *pvh, *patth;
    cudaGetSymbolAddress((void**)&act, g_act);
    cudaGetSymbolAddress((void**)&act2, g_act2);
    cudaGetSymbolAddress((void**)&pw, g_w);
    cudaGetSymbolAddress((void**)&pqh, g_qh);
    cudaGetSymbolAddress((void**)&pkh, g_kh);
    cudaGetSymbolAddress((void**)&pvh, g_vh);
    cudaGetSymbolAddress((void**)&patth, g_atth);
    __half* w3 = pw + (size_t)3 * DIMV * DIMV;

    cudaFuncSetAttribute(gemm_qkv, cudaFuncAttributeMaxDynamicSharedMemorySize, G_SMEM);
    cudaFuncSetAttribute(gemm_wo, cudaFuncAttributeMaxDynamicSharedMemorySize, G_SMEM);
    cudaFuncSetAttribute(attn_flash, cudaFuncAttributeMaxDynamicSharedMemorySize, A_SMEM);

    // all converts in one launch, 4 float4/thread
    conv_all<<<CONV_TOT / 1024, 256>>>(Wq, Wk, Wv, Wo, Q, Kin, pw, act, act2);

    // merged Q + K + V projections
    gemm_qkv<<<dim3(24, MROWS / 128), 256, G_SMEM>>>(
        act, act2, pw, bq, bk, bv, pqh, pkh, pvh);

    // flash attention (fp16 in/out; q-residual from pqh)
    attn_flash<<<dim3(NSEQ / 128, NH * NB), 256, A_SMEM>>>(
        pqh, pkh, pvh, sbias, patth);

    // LN0 -> fp16
    ln_fused<<<MROWS, 256>>>(patth, g0, be0, act);

    // Wo projection with fused u = ln0 + relu(.) epilogue, fp16 out (reuse patth)
    gemm_wo<<<dim3(DIMV / 128, MROWS / 128), 256, G_SMEM>>>(act, w3, bo, patth);

    // final LayerNorm (fp16 in, fp32 out)
    final_kernel<<<MROWS, 256>>>(patth, g1, be1, out);
}

// round 17
// speedup vs baseline: 1.0076x; 1.0076x over previous
#include <cuda_runtime.h>
#include <cuda_fp16.h>
#include <cstdint>
#include <cstddef>

#define DIMV 1024
#define NB 4
#define NSEQ 1024
#define NH 16
#define DH 64
#define MROWS (NB * NSEQ)

// ---------------- scratch (static device globals; no allocs) ----------------
__device__ __half g_act[MROWS * DIMV];       // Q activations / ln0 fp16
__device__ __half g_act2[MROWS * DIMV];      // K activations fp16
__device__ __half g_w[4][DIMV * DIMV];       // Wq, Wk, Wv, Wo fp16
__device__ __half g_qh[MROWS * DIMV];
__device__ __half g_kh[MROWS * DIMV];
__device__ __half g_vh[MROWS * DIMV];
__device__ __half g_atth[MROWS * DIMV];      // attn out fp16, then reused for u fp16

// ======================================================================
// PTX helpers (compute_103-safe)
// ======================================================================
__device__ __forceinline__ uint32_t smem_u32(const void* p) {
    uint32_t a;
    asm("{ .reg .u64 t; cvta.to.shared.u64 t, %1; cvt.u32.u64 %0, t; }" : "=r"(a) : "l"(p));
    return a;
}
__device__ __forceinline__ void cp_async16(uint32_t dst, const void* src) {
    asm volatile("cp.async.cg.shared.global [%0], [%1], 16;" :: "r"(dst), "l"(src));
}
__device__ __forceinline__ void cp_commit() {
    asm volatile("cp.async.commit_group;" ::: "memory");
}
template <int N>
__device__ __forceinline__ void cp_wait() {
    asm volatile("cp.async.wait_group %0;" :: "n"(N) : "memory");
}
__device__ __forceinline__ void ldsm4(uint32_t& r0, uint32_t& r1, uint32_t& r2,
                                      uint32_t& r3, uint32_t addr) {
    asm volatile("ldmatrix.sync.aligned.m8n8.x4.shared.b16 {%0,%1,%2,%3}, [%4];"
                 : "=r"(r0), "=r"(r1), "=r"(r2), "=r"(r3) : "r"(addr));
}
__device__ __forceinline__ void ldsm4t(uint32_t& r0, uint32_t& r1, uint32_t& r2,
                                       uint32_t& r3, uint32_t addr) {
    asm volatile("ldmatrix.sync.aligned.m8n8.x4.trans.shared.b16 {%0,%1,%2,%3}, [%4];"
                 : "=r"(r0), "=r"(r1), "=r"(r2), "=r"(r3) : "r"(addr));
}
__device__ __forceinline__ void mma_f16(float& c0, float& c1, float& c2, float& c3,
                                        uint32_t a0, uint32_t a1, uint32_t a2, uint32_t a3,
                                        uint32_t b0, uint32_t b1) {
    asm volatile(
        "mma.sync.aligned.m16n8k16.row.col.f32.f16.f16.f32 "
        "{%0,%1,%2,%3}, {%4,%5,%6,%7}, {%8,%9}, {%0,%1,%2,%3};"
        : "+f"(c0), "+f"(c1), "+f"(c2), "+f"(c3)
        : "r"(a0), "r"(a1), "r"(a2), "r"(a3), "r"(b0), "r"(b1));
}
__device__ __forceinline__ uint32_t packh(float a, float b) {
    __half2 t = __floats2half2_rn(a, b);
    return *(uint32_t*)&t;
}
__device__ __forceinline__ float2 unpackh(uint32_t u) {
    __half2 h = *(__half2*)&u;
    return __half22float2(h);
}

// ======================================================================
// GEMM core via fp16 HMMA: V[m,n] = sum_k A[m,k]*W[n,k] + bias[n]
// 128x128 tile, BK=32, 8 warps (2x4), 4-stage, one __syncthreads/iter.
// (Proven R13/R15 shape.)
// ======================================================================
#define ROWB 80
#define BUFB (128 * ROWB)       // 10240
#define STAGEB (2 * BUFB)       // 20480
#define G_SMEM (4 * STAGEB)     // 81920

__device__ __forceinline__ void gemm_core(
    uint32_t sb, const __half* __restrict__ ah, const __half* __restrict__ bh,
    int m0, int n0, const float* __restrict__ bias,
    __half* __restrict__ Ch, const __half* __restrict__ lnref) {
    const int tid = threadIdx.x;
    const int lane = tid & 31;
    const int wid = tid >> 5;
    const int wm = wid >> 2;
    const int wn = wid & 3;

    auto issue = [&](int kt, int st) {
        const int k0 = kt * 32;
        const uint32_t base = sb + st * STAGEB;
#pragma unroll
        for (int i = 0; i < 4; i++) {
            const int c = tid + i * 256;
            const int buf = c >> 9;
            const int row = (c & 511) >> 2;
            const int seg = c & 3;
            const __half* src = (buf ? bh + (size_t)(n0 + row) * DIMV
                                     : ah + (size_t)(m0 + row) * DIMV) + k0 + seg * 8;
            cp_async16(base + buf * BUFB + row * ROWB + seg * 16, src);
        }
        cp_commit();
    };

    float acc[4][4][4];
#pragma unroll
    for (int mt = 0; mt < 4; mt++)
#pragma unroll
        for (int nt = 0; nt < 4; nt++)
#pragma unroll
            for (int r = 0; r < 4; r++) acc[mt][nt][r] = 0.0f;

    issue(0, 0);
    issue(1, 1);
    issue(2, 2);

    const int NKT = DIMV / 32;
    for (int kt = 0; kt < NKT; ++kt) {
        if (kt < NKT - 2)       cp_wait<2>();
        else if (kt == NKT - 2) cp_wait<1>();
        else                    cp_wait<0>();
        __syncthreads();

        const uint32_t stg = sb + (kt & 3) * STAGEB;
        const int arow = lane & 15;
        const int akh = lane >> 4;
        const int bprow = ((lane >> 4) << 3) + (lane & 7);
        const int bpkh = (lane >> 3) & 1;

#pragma unroll
        for (int ks = 0; ks < 2; ks++) {
            const uint32_t koff = ks * 32;
            uint32_t fa[4][4];
#pragma unroll
            for (int mt = 0; mt < 4; mt++) {
                const uint32_t ra = stg +
                    (uint32_t)(wm * 64 + mt * 16 + arow) * ROWB + koff + akh * 16;
                ldsm4(fa[mt][0], fa[mt][1], fa[mt][2], fa[mt][3], ra);
            }
#pragma unroll
            for (int ntp = 0; ntp < 2; ntp++) {
                const uint32_t rb = stg + BUFB +
                    (uint32_t)(wn * 32 + ntp * 16 + bprow) * ROWB + koff + bpkh * 16;
                uint32_t b0, b1, b2, b3;
                ldsm4(b0, b1, b2, b3, rb);
                const int nt = ntp * 2;
#pragma unroll
                for (int mt = 0; mt < 4; mt++) {
                    mma_f16(acc[mt][nt][0], acc[mt][nt][1], acc[mt][nt][2], acc[mt][nt][3],
                            fa[mt][0], fa[mt][1], fa[mt][2], fa[mt][3], b0, b1);
                    mma_f16(acc[mt][nt + 1][0], acc[mt][nt + 1][1],
                            acc[mt][nt + 1][2], acc[mt][nt + 1][3],
                            fa[mt][0], fa[mt][1], fa[mt][2], fa[mt][3], b2, b3);
                }
            }
        }
        if (kt + 3 < NKT) issue(kt + 3, (kt + 3) & 3);
    }

    const int cr = lane >> 2;
    const int cc = (lane & 3) * 2;
#pragma unroll
    for (int nt = 0; nt < 4; nt++) {
        const int col = n0 + wn * 32 + nt * 8 + cc;
        const float2 bf = *(const float2*)(bias + col);
#pragma unroll
        for (int mt = 0; mt < 4; mt++) {
            const int r0 = m0 + wm * 64 + mt * 16 + cr;
            float v00 = acc[mt][nt][0] + bf.x, v01 = acc[mt][nt][1] + bf.y;
            float v10 = acc[mt][nt][2] + bf.x, v11 = acc[mt][nt][3] + bf.y;
            if (lnref) {
                float2 l0 = unpackh(*(const uint32_t*)(lnref + (size_t)r0 * DIMV + col));
                float2 l1 = unpackh(*(const uint32_t*)(lnref + (size_t)(r0 + 8) * DIMV + col));
                v00 = l0.x + fmaxf(v00, 0.0f);
                v01 = l0.y + fmaxf(v01, 0.0f);
                v10 = l1.x + fmaxf(v10, 0.0f);
                v11 = l1.y + fmaxf(v11, 0.0f);
            }
            *(uint32_t*)(Ch + (size_t)r0 * DIMV + col) = packh(v00, v01);
            *(uint32_t*)(Ch + (size_t)(r0 + 8) * DIMV + col) = packh(v10, v11);
        }
    }
}

__global__ __launch_bounds__(256, 2)
void gemm_qkv(const __half* __restrict__ act, const __half* __restrict__ act2,
              const __half* __restrict__ w,
              const float* __restrict__ bq, const float* __restrict__ bk,
              const float* __restrict__ bv,
              __half* __restrict__ pqh, __half* __restrict__ pkh,
              __half* __restrict__ pvh) {
    extern __shared__ char smc[];
    const uint32_t sb = smem_u32(smc);
    const int x = blockIdx.x;
    const int m0 = blockIdx.y * 128;
    const __half *A, *B;
    const float* bias;
    __half* Ch;
    int n0;
    if (x < 8) {
        A = act;  B = w;                           bias = bq; Ch = pqh; n0 = x * 128;
    } else if (x < 16) {
        A = act2; B = w + (size_t)DIMV * DIMV;     bias = bk; Ch = pkh; n0 = (x - 8) * 128;
    } else {
        A = act2; B = w + (size_t)2 * DIMV * DIMV; bias = bv; Ch = pvh; n0 = (x - 16) * 128;
    }
    gemm_core(sb, A, B, m0, n0, bias, Ch, nullptr);
}

__global__ __launch_bounds__(256, 2)
void gemm_wo(const __half* __restrict__ act, const __half* __restrict__ w3,
             const float* __restrict__ bo, __half* __restrict__ u) {
    extern __shared__ char smc[];
    const uint32_t sb = smem_u32(smc);
    gemm_core(sb, act, w3, blockIdx.y * 128, blockIdx.x * 128, bo, u, act);
}

// ======================================================================
// One-shot convert: 4 weights + Q act + K act -> fp16 (4 float4/thread ILP)
// ======================================================================
#define W4TOT (DIMV * DIMV)
#define ACTTOT (MROWS * DIMV)
#define CONV_TOT (4 * W4TOT / 4 + 2 * ACTTOT / 4)
__global__ __launch_bounds__(256) void conv_all(const float* __restrict__ Wq,
                                                const float* __restrict__ Wk,
                                                const float* __restrict__ Wv,
                                                const float* __restrict__ Wo,
                                                const float* __restrict__ Qa,
                                                const float* __restrict__ Ka,
                                                __half* __restrict__ wout,
                                                __half* __restrict__ qout,
                                                __half* __restrict__ kout) {
    const int W4Q = W4TOT / 4;
    const int A4 = ACTTOT / 4;
    auto locate = [&](int i, const float*& src, __half*& dst, int& off) {
        if (i < 4 * W4Q) {
            const int wsel = i >> 18;
            off = i & (W4Q - 1);
            src = (wsel == 0) ? Wq : (wsel == 1) ? Wk : (wsel == 2) ? Wv : Wo;
            dst = wout + (size_t)wsel * W4TOT;
        } else if (i < 4 * W4Q + A4) {
            off = i - 4 * W4Q;
            src = Qa;
            dst = qout;
        } else {
            off = i - 4 * W4Q - A4;
            src = Ka;
            dst = kout;
        }
    };
    const int base = blockIdx.x * 1024 + threadIdx.x;
    const float* s[4];
    __half* d[4];
    int o[4];
#pragma unroll
    for (int j = 0; j < 4; j++) locate(base + j * 256, s[j], d[j], o[j]);
    float4 v[4];
#pragma unroll
    for (int j = 0; j < 4; j++) v[j] = ((const float4*)s[j])[o[j]];
#pragma unroll
    for (int j = 0; j < 4; j++) {
        uint2 r = {packh(v[j].x, v[j].y), packh(v[j].z, v[j].w)};
        ((uint2*)d[j])[o[j]] = r;
    }
}

// ======================================================================
// Flash attention via fp16 HMMA (proven R9/R13/R15 structure, unchanged)
// ======================================================================
#define AROWB 144
#define ABUF (128 * AROWB)          // 18432
#define ASTAGE (2 * ABUF)           // 36864
#define AQOFF (2 * ASTAGE)          // 73728
#define A_SMEM (AQOFF + ABUF)       // 92160

__global__ __launch_bounds__(256, 2)
void attn_flash(const __half* __restrict__ qh, const __half* __restrict__ kh,
                const __half* __restrict__ vh, const float* __restrict__ bias,
                __half* __restrict__ out) {
    extern __shared__ char smc[];
    const uint32_t sb = smem_u32(smc);
    const int tid = threadIdx.x;
    const int lane = tid & 31;
    const int w = tid >> 5;
    const int q0 = blockIdx.x * 128;
    const int hb = blockIdx.y;
    const int h = hb >> 2;
    const int b = hb & 3;
    const size_t rowbase = (size_t)b * NSEQ;
    const int hcol = h * DH;

    {
#pragma unroll
        for (int i = 0; i < 4; i++) {
            const int c = tid + i * 256;
            const int row = c >> 3;
            const int seg = c & 7;
            cp_async16(sb + AQOFF + row * AROWB + seg * 16,
                       qh + (rowbase + q0 + row) * DIMV + hcol + seg * 8);
        }
        cp_commit();
    }
    auto issueKV = [&](int k0, int st) {
#pragma unroll
        for (int i = 0; i < 8; i++) {
            const int c = tid + i * 256;
            const int buf = c >> 10;
            const int row = (c >> 3) & 127;
            const int seg = c & 7;
            const __half* src = (buf ? vh : kh) + (rowbase + k0 + row) * DIMV + hcol + seg * 8;
            cp_async16(sb + st * ASTAGE + buf * ABUF + row * AROWB + seg * 16, src);
        }
        cp_commit();
    };
    issueKV(0, 0);

    float oacc[8][4];
#pragma unroll
    for (int d = 0; d < 8; d++)
#pragma unroll
        for (int r = 0; r < 4; r++) oacc[d][r] = 0.0f;
    float lsum0 = 0.0f, lsum1 = 0.0f;
    const float scale = 0.03125f;
    const float* bb = bias + ((size_t)hb * NSEQ + q0) * NSEQ;
    const int r_lo = lane >> 2;
    const int c_lo = (lane & 3) * 2;
    const size_t brow0 = (size_t)(w * 16 + r_lo) * NSEQ;

    float2 bA[8], bB[8];
    auto load_bias_q = [&](float2* slot, int ckx, int gq) {
        const float* bcol = bb + ckx * 128 + gq * 32;
#pragma unroll
        for (int nl = 0; nl < 4; nl++) {
            slot[nl * 2] = __ldcs((const float2*)(bcol + brow0 + nl * 8 + c_lo));
            slot[nl * 2 + 1] =
                __ldcs((const float2*)(bcol + brow0 + 8 * NSEQ + nl * 8 + c_lo));
        }
    };
    load_bias_q(bA, 0, 0);
    load_bias_q(bB, 0, 1);

    uint32_t qf[2][2][4];
    bool qloaded = false;

    for (int ck = 0; ck < 8; ck++) {
        const int st = ck & 1;
        if (ck + 1 < 8) {
            issueKV((ck + 1) * 128, (ck + 1) & 1);
            cp_wait<1>();
        } else {
            cp_wait<0>();
        }
        __syncthreads();
        const uint32_t kbase = sb + st * ASTAGE;

        if (!qloaded) {
            qloaded = true;
            const int arow = lane & 15;
            const int akh = lane >> 4;
#pragma unroll
            for (int ksp = 0; ksp < 2; ksp++) {
                const uint32_t ra = sb + AQOFF +
                    (uint32_t)(w * 16 + arow) * AROWB + ksp * 64 + akh * 16;
                ldsm4(qf[ksp][0][0], qf[ksp][0][1], qf[ksp][0][2], qf[ksp][0][3], ra);
                ldsm4(qf[ksp][1][0], qf[ksp][1][1], qf[ksp][1][2], qf[ksp][1][3], ra + 32);
            }
        }

#pragma unroll
        for (int h2 = 0; h2 < 2; h2++) {
#pragma unroll
            for (int qq = 0; qq < 2; qq++) {
                float sacc[4][4];
#pragma unroll
                for (int nl = 0; nl < 4; nl++) {
                    sacc[nl][0] = 0.0f; sacc[nl][1] = 0.0f;
                    sacc[nl][2] = 0.0f; sacc[nl][3] = 0.0f;
                }
#pragma unroll
                for (int ksp = 0; ksp < 2; ksp++) {
#pragma unroll
                    for (int nl = 0; nl < 4; nl++) {
                        const uint32_t rb = kbase +
                            (uint32_t)(h2 * 64 + qq * 32 + nl * 8 + (lane & 7)) * AROWB +
                            ksp * 64 + ((lane >> 3) & 3) * 16;
                        uint32_t b0, b1, b2, b3;
                        ldsm4(b0, b1, b2, b3, rb);
                        mma_f16(sacc[nl][0], sacc[nl][1], sacc[nl][2], sacc[nl][3],
                                qf[ksp][0][0], qf[ksp][0][1], qf[ksp][0][2], qf[ksp][0][3],
                                b0, b1);
                        mma_f16(sacc[nl][0], sacc[nl][1], sacc[nl][2], sacc[nl][3],
                                qf[ksp][1][0], qf[ksp][1][1], qf[ksp][1][2], qf[ksp][1][3],
                                b2, b3);
                    }
                }

                float2* slot = qq ? bB : bA;
                uint32_t pa[2][4];
#pragma unroll
                for (int nl = 0; nl < 4; nl++) {
                    float2 b01 = slot[nl * 2];
                    float2 b23 = slot[nl * 2 + 1];
                    float p0 = __expf(fmaf(sacc[nl][0], scale, b01.x));
                    float p1 = __expf(fmaf(sacc[nl][1], scale, b01.y));
                    float p2 = __expf(fmaf(sacc[nl][2], scale, b23.x));
                    float p3 = __expf(fmaf(sacc[nl][3], scale, b23.y));
                    lsum0 += p0 + p1;
                    lsum1 += p2 + p3;
                    pa[nl >> 1][(nl & 1) * 2] = packh(p0, p1);
                    pa[nl >> 1][(nl & 1) * 2 + 1] = packh(p2, p3);
                }

                {
                    const int gq = h2 * 2 + qq;
                    int nq = gq + 2;
                    int nck = ck;
                    if (nq >= 4) { nq -= 4; nck++; }
                    if (nck < 8) load_bias_q(slot, nck, nq);
                }

#pragma unroll
                for (int kt = 0; kt < 2; kt++) {
#pragma unroll
                    for (int dtp = 0; dtp < 4; dtp++) {
                        const int dt = dtp * 2;
                        const uint32_t rv = kbase + ABUF +
                            (uint32_t)(h2 * 64 + qq * 32 + kt * 16 + (lane & 15)) * AROWB +
                            (dt + (lane >> 4)) * 16;
                        uint32_t v0, v1, v2, v3;
                        ldsm4t(v0, v1, v2, v3, rv);
                        mma_f16(oacc[dt][0], oacc[dt][1], oacc[dt][2], oacc[dt][3],
                                pa[kt][0], pa[kt][1], pa[kt][2], pa[kt][3], v0, v1);
                        mma_f16(oacc[dt + 1][0], oacc[dt + 1][1],
                                oacc[dt + 1][2], oacc[dt + 1][3],
                                pa[kt][0], pa[kt][1], pa[kt][2], pa[kt][3], v2, v3);
                    }
                }
            }
        }
        __syncthreads();
    }

    lsum0 += __shfl_xor_sync(0xffffffffu, lsum0, 1);
    lsum0 += __shfl_xor_sync(0xffffffffu, lsum0, 2);
    lsum1 += __shfl_xor_sync(0xffffffffu, lsum1, 1);
    lsum1 += __shfl_xor_sync(0xffffffffu, lsum1, 2);
    const float inv0 = 1.0f / lsum0;
    const float inv1 = 1.0f / lsum1;
    const size_t r0g = rowbase + q0 + w * 16 + r_lo;
#pragma unroll
    for (int dt = 0; dt < 8; dt++) {
        const int col = hcol + dt * 8 + c_lo;
        float2 q01 = unpackh(*(const uint32_t*)(qh + r0g * DIMV + col));
        float2 q23 = unpackh(*(const uint32_t*)(qh + (r0g + 8) * DIMV + col));
        *(uint32_t*)(out + r0g * DIMV + col) =
            packh(q01.x + oacc[dt][0] * inv0, q01.y + oacc[dt][1] * inv0);
        *(uint32_t*)(out + (r0g + 8) * DIMV + col) =
            packh(q23.x + oacc[dt][2] * inv1, q23.y + oacc[dt][3] * inv1);
    }
}

// ======================================================================
// LayerNorm (fp16 in) -> fp16 out; cross-warp reduce via 8-lane shuffle
// ======================================================================
__global__ __launch_bounds__(256) void ln_fused(const __half* __restrict__ x,
                                                const float* __restrict__ gamma,
                                                const float* __restrict__ beta,
                                                __half* __restrict__ hi) {
    const int row = blockIdx.x;
    const int tid = threadIdx.x;
    uint2 raw = *(const uint2*)(x + (size_t)row * DIMV + tid * 4);
    float2 v01 = unpackh(raw.x);
    float2 v23 = unpackh(raw.y);
    float4 v = {v01.x, v01.y, v23.x, v23.y};
    float s = v.x + v.y + v.z + v.w;
    float sq = v.x * v.x + v.y * v.y + v.z * v.z + v.w * v.w;
#pragma unroll
    for (int o = 16; o; o >>= 1) {
        s += __shfl_xor_sync(0xffffffffu, s, o);
        sq += __shfl_xor_sync(0xffffffffu, sq, o);
    }
    __shared__ float sh[18];
    int wid = tid >> 5, lane = tid & 31;
    if (lane == 0) { sh[wid] = s; sh[8 + wid] = sq; }
    __syncthreads();
    if (tid < 8) {
        float S = sh[tid];
        float SQ = sh[8 + tid];
#pragma unroll
        for (int o = 4; o; o >>= 1) {
            S += __shfl_xor_sync(0x000000ffu, S, o);
            SQ += __shfl_xor_sync(0x000000ffu, SQ, o);
        }
        if (tid == 0) {
            float m = S * (1.0f / DIMV);
            float var = SQ * (1.0f / DIMV) - m * m;
            sh[16] = m;
            sh[17] = rsqrtf(var + 1e-5f);
        }
    }
    __syncthreads();
    float m = sh[16], rs = sh[17];
    float4 gv = *(const float4*)(gamma + tid * 4);
    float4 bv = *(const float4*)(beta + tid * 4);
    float o0 = (v.x - m) * rs * gv.x + bv.x;
    float o1 = (v.y - m) * rs * gv.y + bv.y;
    float o2 = (v.z - m) * rs * gv.z + bv.z;
    float o3 = (v.w - m) * rs * gv.w + bv.w;
    uint2 r = {packh(o0, o1), packh(o2, o3)};
    *(uint2*)(hi + (size_t)row * DIMV + tid * 4) = r;
}

// Final: pure LayerNorm of u (fp16 in, fp32 out); same shuffle reduce
__global__ __launch_bounds__(256) void final_kernel(const __half* __restrict__ x,
                                                    const float* __restrict__ gamma,
                                                    const float* __restrict__ beta,
                                                    float* __restrict__ y) {
    const int row = blockIdx.x;
    const int tid = threadIdx.x;
    uint2 raw = *(const uint2*)(x + (size_t)row * DIMV + tid * 4);
    float2 v01 = unpackh(raw.x);
    float2 v23 = unpackh(raw.y);
    float4 v = {v01.x, v01.y, v23.x, v23.y};
    float s = v.x + v.y + v.z + v.w;
    float sq = v.x * v.x + v.y * v.y + v.z * v.z + v.w * v.w;
#pragma unroll
    for (int o = 16; o; o >>= 1) {
        s += __shfl_xor_sync(0xffffffffu, s, o);
        sq += __shfl_xor_sync(0xffffffffu, sq, o);
    }
    __shared__ float sh[18];
    int wid = tid >> 5, lane = tid & 31;
    if (lane == 0) { sh[wid] = s; sh[8 + wid] = sq; }
    __syncthreads();
    if (tid < 8) {
        float S = sh[tid];
        float SQ = sh[8 + tid];
#pragma unroll
        for (int o = 4; o; o >>= 1) {
            S += __shfl_xor_sync(0x000000ffu, S, o);
            SQ += __shfl_xor_sync(0x000000ffu, SQ, o);
        }
        if (tid == 0) {
            float m = S * (1.0f / DIMV);
            float var = SQ * (1.0f / DIMV) - m * m;
            sh[16] = m;
            sh[17] = rsqrtf(var + 1e-5f);
        }
    }
    __syncthreads();
    float m = sh[16], rs = sh[17];
    float4 gv = *(const float4*)(gamma + tid * 4);
    float4 bv = *(const float4*)(beta + tid * 4);
    float4 o;
    o.x = (v.x - m) * rs * gv.x + bv.x;
    o.y = (v.y - m) * rs * gv.y + bv.y;
    o.z = (v.z - m) * rs * gv.z + bv.z;
    o.w = (v.w - m) * rs * gv.w + bv.w;
    *(float4*)(y + (size_t)row * DIMV + tid * 4) = o;
}

// ======================================================================
extern "C" void kernel_launch(void* const* d_in, const int* in_sizes, int n_in,
                              void* d_out, int out_size) {
    (void)in_sizes; (void)n_in; (void)out_size;
    const float* Q   = (const float*)d_in[0];
    const float* Kin = (const float*)d_in[1];
    const float* sbias = (const float*)d_in[2];
    const float* Wq  = (const float*)d_in[3];
    const float* bq  = (const float*)d_in[4];
    const float* Wk  = (const float*)d_in[5];
    const float* bk  = (const float*)d_in[6];
    const float* Wv  = (const float*)d_in[7];
    const float* bv  = (const float*)d_in[8];
    const float* Wo  = (const float*)d_in[9];
    const float* bo  = (const float*)d_in[10];
    const float* g0  = (const float*)d_in[11];
    const float* be0 = (const float*)d_in[12];
    const float* g1  = (const float*)d_in[13];
    const float* be1 = (const float*)d_in[14];
    float* out = (float*)d_out;

    __half *act, *act2, *pw, *pqh, *pkh, *pvh, *patth;
    cudaGetSymbolAddress((void**)&act, g_act);
    cudaGetSymbolAddress((void**)&act2, g_act2);
    cudaGetSymbolAddress((void**)&pw, g_w);
    cudaGetSymbolAddress((void**)&pqh, g_qh);
    cudaGetSymbolAddress((void**)&pkh, g_kh);
    cudaGetSymbolAddress((void**)&pvh, g_vh);
    cudaGetSymbolAddress((void**)&patth, g_atth);
    __half* w3 = pw + (size_t)3 * DIMV * DIMV;

    cudaFuncSetAttribute(gemm_qkv, cudaFuncAttributeMaxDynamicSharedMemorySize, G_SMEM);
    cudaFuncSetAttribute(gemm_wo, cudaFuncAttributeMaxDynamicSharedMemorySize, G_SMEM);
    cudaFuncSetAttribute(attn_flash, cudaFuncAttributeMaxDynamicSharedMemorySize, A_SMEM);

    // all converts in one launch, 4 float4/thread
    conv_all<<<CONV_TOT / 1024, 256>>>(Wq, Wk, Wv, Wo, Q, Kin, pw, act, act2);

    // merged Q + K + V projections
    gemm_qkv<<<dim3(24, MROWS / 128), 256, G_SMEM>>>(
        act, act2, pw, bq, bk, bv, pqh, pkh, pvh);

    // flash attention (fp16 in/out; q-residual from pqh)
    attn_flash<<<dim3(NSEQ / 128, NH * NB), 256, A_SMEM>>>(
        pqh, pkh, pvh, sbias, patth);

    // LN0 -> fp16
    ln_fused<<<MROWS, 256>>>(patth, g0, be0, act);

    // Wo projection with fused u = ln0 + relu(.) epilogue, fp16 out (reuse patth)
    gemm_wo<<<dim3(DIMV / 128, MROWS / 128), 256, G_SMEM>>>(act, w3, bo, patth);

    // final LayerNorm (fp16 in, fp32 out)
    final_kernel<<<MROWS, 256>>>(patth, g1, be1, out);
}